// round 14
// baseline (speedup 1.0000x reference)
#include <cuda_runtime.h>
#include <cuda_fp16.h>
#include <math.h>

#define B   16
#define N   1024
#define MP  1024
#define EPS_F    0.1f
#define INV_EPS  10.0f
#define MAX_ITER 100
#define NCOMP 128           // compute blocks (16 batches x 8); all co-resident
#define NCOPY 20            // dedicated copy blocks on the idle SMs
#define GRID  (NCOMP + NCOPY)
#define TPB  256
#define RPB  128            // rows per block
#define RPW  16             // rows per warp
#define PB   8              // blocks per batch

// ---------------- static device scratch (no allocations allowed) ------------
__device__ __half g_Kh[(size_t)B * N * MP];     // 32 MB: exp(-C/eps) in fp16
__device__ float  g_part[2][B][PB][MP];         // double-buffered column partials
__device__ float  g_errpart[2][NCOMP];
__device__ float  g_costpart[NCOMP];
__device__ int          g_cnt;
__device__ volatile int g_gen;

// -------- software grid barrier (128 compute blocks, 1/SM, all resident) ----
__device__ __forceinline__ void gridbar() {
    __syncthreads();
    if (threadIdx.x == 0) {
        __threadfence();
        int g = g_gen;
        if (atomicAdd(&g_cnt, 1) == NCOMP - 1) {
            g_cnt = 0;
            __threadfence();
            g_gen = g + 1;
        } else {
            while (g_gen == g) __nanosleep(64);
        }
        __threadfence();
    }
    __syncthreads();
}

__device__ __forceinline__ void h8_to_f8(const uint4 v, float* f) {
    float2 a = __half22float2(*(const __half2*)&v.x);
    float2 b = __half22float2(*(const __half2*)&v.y);
    float2 c = __half22float2(*(const __half2*)&v.z);
    float2 d = __half22float2(*(const __half2*)&v.w);
    f[0]=a.x; f[1]=a.y; f[2]=b.x; f[3]=b.y; f[4]=c.x; f[5]=c.y; f[6]=d.x; f[7]=d.y;
}

__global__ void __launch_bounds__(TPB, 1)
k_sinkhorn(const float* __restrict__ C, float* __restrict__ out)
{
    const int bid = blockIdx.x;
    const int tid = threadIdx.x;

    const float4* C4   = (const float4*)C;
    float*  outCost = out;
    float4* outPi   = (float4*)(out + B);
    float4* outC    = (float4*)(out + B + (size_t)B * N * MP);

    // ================= Copy blocks: stream C -> outC, then exit =============
    if (bid >= NCOMP) {
        const size_t TOT = (size_t)B * N * 256;          // total float4 count
        const int j = bid - NCOMP;                       // 0..NCOPY-1
        size_t s = TOT * (size_t)j / NCOPY;
        size_t e = TOT * (size_t)(j + 1) / NCOPY;
        size_t i = s + tid;
        // main loop: 4-deep batches for MLP
        for (; i + 3 * TPB < e; i += 4 * TPB) {
            float4 v0 = __ldcs(C4 + i);
            float4 v1 = __ldcs(C4 + i + TPB);
            float4 v2 = __ldcs(C4 + i + 2 * TPB);
            float4 v3 = __ldcs(C4 + i + 3 * TPB);
            __stcs(outC + i,           v0);
            __stcs(outC + i + TPB,     v1);
            __stcs(outC + i + 2 * TPB, v2);
            __stcs(outC + i + 3 * TPB, v3);
        }
        for (; i < e; i += TPB) {
            float4 v = __ldcs(C4 + i);
            __stcs(outC + i, v);
        }
        return;
    }

    // ================= Compute blocks (R8-proven schedule) ===================
    __shared__ float sb[MP];             // current b (exp(v/eps)) for this batch
    __shared__ float sT[8][MP];          // per-warp column partials
    __shared__ float sU[RPB];
    __shared__ float sA[RPB];
    __shared__ float sred[TPB];

    const int b   = bid >> 3;            // batch 0..15
    const int ib  = bid & 7;             // block-in-batch 0..7
    const int w   = tid >> 5;            // warp 0..7
    const int l   = tid & 31;
    const int rowBase = (b << 10) + (ib << 7);   // 128 rows per block
    const int wrow    = rowBase + w * RPW;       // this warp's 16 rows

    const float MU   = 1.0f / 1024.0f + 1e-8f;
    const float LOGM = logf(MU);

    if (tid < RPB) { sU[tid] = 0.f; sA[tid] = 0.f; }
    ((float4*)sb)[tid] = make_float4(1.f, 1.f, 1.f, 1.f);   // b0 = 1
    __syncthreads();

    uint4* K4 = (uint4*)g_Kh;            // 8 halfs/uint4, 128 uint4 per row

    int par = 0;
    for (int t = 0; t < MAX_ITER; t++) {
        // -------- cache b in registers: lane covers cols (k*32+l)*8 + e -----
        float bb[4][8];
        #pragma unroll
        for (int k = 0; k < 4; k++) {
            float4 p0 = ((const float4*)sb)[(((k << 5) + l) << 1)];
            float4 p1 = ((const float4*)sb)[(((k << 5) + l) << 1) + 1];
            bb[k][0]=p0.x; bb[k][1]=p0.y; bb[k][2]=p0.z; bb[k][3]=p0.w;
            bb[k][4]=p1.x; bb[k][5]=p1.y; bb[k][6]=p1.z; bb[k][7]=p1.w;
        }
        float Tacc[4][8];
        #pragma unroll
        for (int k = 0; k < 4; k++)
            #pragma unroll
            for (int e = 0; e < 8; e++) Tacc[k][e] = 0.f;
        float du = 0.f;

        if (t == 0) {
            // ---- first pass: build fp16 K from C ----
            for (int r = 0; r < RPW; r++) {
                size_t qb = (size_t)(wrow + r) << 7;
                float kf[4][8];
                #pragma unroll
                for (int k = 0; k < 4; k++) {
                    size_t q = qb + (k << 5) + l;
                    float4 c0 = C4[q << 1];
                    float4 c1 = C4[(q << 1) + 1];
                    kf[k][0]=__expf(-c0.x*INV_EPS); kf[k][1]=__expf(-c0.y*INV_EPS);
                    kf[k][2]=__expf(-c0.z*INV_EPS); kf[k][3]=__expf(-c0.w*INV_EPS);
                    kf[k][4]=__expf(-c1.x*INV_EPS); kf[k][5]=__expf(-c1.y*INV_EPS);
                    kf[k][6]=__expf(-c1.z*INV_EPS); kf[k][7]=__expf(-c1.w*INV_EPS);
                    uint4 kv;
                    __half2 h;
                    h=__floats2half2_rn(kf[k][0],kf[k][1]); kv.x=*(unsigned*)&h;
                    h=__floats2half2_rn(kf[k][2],kf[k][3]); kv.y=*(unsigned*)&h;
                    h=__floats2half2_rn(kf[k][4],kf[k][5]); kv.z=*(unsigned*)&h;
                    h=__floats2half2_rn(kf[k][6],kf[k][7]); kv.w=*(unsigned*)&h;
                    K4[q] = kv;
                    // use the fp16-rounded values so iterations are consistent
                    h8_to_f8(kv, kf[k]);
                }
                float s = 0.f;
                #pragma unroll
                for (int k = 0; k < 4; k++)
                    #pragma unroll
                    for (int e = 0; e < 8; e++) s = fmaf(kf[k][e], bb[k][e], s);
                #pragma unroll
                for (int o = 16; o; o >>= 1) s += __shfl_xor_sync(~0u, s, o);
                float a = MU / s;
                if (l == 0) {
                    float unew = EPS_F * (LOGM - logf(s));
                    int ri = w * RPW + r;
                    du += fabsf(unew - sU[ri]);
                    sU[ri] = unew; sA[ri] = a;
                }
                #pragma unroll
                for (int k = 0; k < 4; k++)
                    #pragma unroll
                    for (int e = 0; e < 8; e++)
                        Tacc[k][e] = fmaf(a, kf[k][e], Tacc[k][e]);
            }
        } else {
            // ---- steady state: fp16 K, double-buffered loads ----
            uint4 kq[4];
            {
                size_t qb = (size_t)wrow << 7;
                #pragma unroll
                for (int k = 0; k < 4; k++) kq[k] = K4[qb + (k << 5) + l];
            }
            for (int r = 0; r < RPW; r++) {
                uint4 kn[4];
                if (r + 1 < RPW) {
                    size_t qn = (size_t)(wrow + r + 1) << 7;
                    #pragma unroll
                    for (int k = 0; k < 4; k++) kn[k] = K4[qn + (k << 5) + l];
                }
                float kf[4][8];
                #pragma unroll
                for (int k = 0; k < 4; k++) h8_to_f8(kq[k], kf[k]);
                float s = 0.f;
                #pragma unroll
                for (int k = 0; k < 4; k++)
                    #pragma unroll
                    for (int e = 0; e < 8; e++) s = fmaf(kf[k][e], bb[k][e], s);
                #pragma unroll
                for (int o = 16; o; o >>= 1) s += __shfl_xor_sync(~0u, s, o);
                float a = MU / s;
                if (l == 0) {
                    float unew = EPS_F * (LOGM - logf(s));
                    int ri = w * RPW + r;
                    du += fabsf(unew - sU[ri]);
                    sU[ri] = unew; sA[ri] = a;
                }
                #pragma unroll
                for (int k = 0; k < 4; k++)
                    #pragma unroll
                    for (int e = 0; e < 8; e++)
                        Tacc[k][e] = fmaf(a, kf[k][e], Tacc[k][e]);
                if (r + 1 < RPW) {
                    #pragma unroll
                    for (int k = 0; k < 4; k++) kq[k] = kn[k];
                }
            }
        }

        // -------- block-combine 8 warps' column partials (deterministic) ----
        {
            float4* me = (float4*)sT[w];
            #pragma unroll
            for (int k = 0; k < 4; k++) {
                me[(((k << 5) + l) << 1)]     = make_float4(Tacc[k][0], Tacc[k][1], Tacc[k][2], Tacc[k][3]);
                me[(((k << 5) + l) << 1) + 1] = make_float4(Tacc[k][4], Tacc[k][5], Tacc[k][6], Tacc[k][7]);
            }
            if (l == 0) sred[w] = du;
        }
        __syncthreads();
        {
            float4 Tj = ((const float4*)sT[0])[tid];
            #pragma unroll
            for (int ww = 1; ww < 8; ww++) {
                float4 x = ((const float4*)sT[ww])[tid];
                Tj.x += x.x; Tj.y += x.y; Tj.z += x.z; Tj.w += x.w;
            }
            ((float4*)g_part[par][b][ib])[tid] = Tj;
        }
        if (tid == 0) {
            float e = 0.f;
            #pragma unroll
            for (int ww = 0; ww < 8; ww++) e += sred[ww];
            g_errpart[par][bid] = e;
        }

        gridbar();

        // -------- v update: combine 8 block-partials (redundant per block) --
        float4 T = make_float4(0.f, 0.f, 0.f, 0.f);
        #pragma unroll
        for (int kk = 0; kk < PB; kk++) {
            float4 x = __ldcg(((const float4*)g_part[par][b][kk]) + tid);
            T.x += x.x; T.y += x.y; T.z += x.z; T.w += x.w;
        }
        float4 bbn;
        bbn.x = MU / T.x; bbn.y = MU / T.y; bbn.z = MU / T.z; bbn.w = MU / T.w;

        // deterministic err reduction
        sred[tid] = (tid < NCOMP) ? __ldcg(&g_errpart[par][tid]) : 0.f;
        __syncthreads();
        for (int o = 128; o; o >>= 1) {
            if (tid < o) sred[tid] += sred[tid + o];
            __syncthreads();
        }
        float err = sred[0];

        ((float4*)sb)[tid] = bbn;
        __syncthreads();

        if (err < 0.1f * (float)B) break;    // err/B < THRESH
        par ^= 1;
    }

    // ============= Epilogue: pi = a*b*exp(-C/eps), cost (outC by copiers) ===
    const float4* sb4 = (const float4*)sb;

    float cost = 0.f;
    for (int r = 0; r < RPW; r++) {
        int row = wrow + r;
        size_t f4 = (size_t)row << 8;
        float a = sA[w * RPW + r];
        #pragma unroll
        for (int k = 0; k < 8; k++) {
            int q = (k << 5) + l;
            float4 c  = C4[f4 + q];
            float4 bv = sb4[q];
            float4 p;
            p.x = a * bv.x * __expf(-c.x * INV_EPS);
            p.y = a * bv.y * __expf(-c.y * INV_EPS);
            p.z = a * bv.z * __expf(-c.z * INV_EPS);
            p.w = a * bv.w * __expf(-c.w * INV_EPS);
            __stcs(&outPi[f4 + q], p);
            cost += p.x * c.x + p.y * c.y + p.z * c.z + p.w * c.w;
        }
    }
    sred[tid] = cost;
    __syncthreads();
    for (int o = 128; o; o >>= 1) {
        if (tid < o) sred[tid] += sred[tid + o];
        __syncthreads();
    }
    if (tid == 0) g_costpart[bid] = sred[0];

    gridbar();

    if (bid == 0 && tid < B) {               // deterministic final cost sum
        float cs = 0.f;
        #pragma unroll
        for (int kk = 0; kk < PB; kk++)
            cs += __ldcg(&g_costpart[(tid << 3) + kk]);
        outCost[tid] = cs;
    }
}

// ---------------- launch -----------------------------------------------------
extern "C" void kernel_launch(void* const* d_in, const int* in_sizes, int n_in,
                              void* d_out, int out_size) {
    const float* C = nullptr;
    for (int i = 0; i < n_in; i++)
        if (in_sizes[i] == B * N * MP) C = (const float*)d_in[i];
    k_sinkhorn<<<GRID, TPB>>>(C, (float*)d_out);
    (void)out_size;
}

// round 15
// speedup vs baseline: 1.9100x; 1.9100x over previous
#include <cuda_runtime.h>
#include <cuda_fp16.h>
#include <math.h>

#define B   16
#define N   1024
#define MP  1024
#define EPS_F    0.1f
#define INV_EPS  10.0f
#define MAX_ITER 100
#define GRID 128            // 16 batches x 8 blocks; 1 CTA/SM, all co-resident
#define TPB  256
#define RPB  128            // rows per block
#define RPW  16             // rows per warp
#define PB   8              // blocks per batch

// ---------------- static device scratch (no allocations allowed) ------------
__device__ __half g_Kh[(size_t)B * N * MP];     // 32 MB: exp(-C/eps) in fp16
__device__ float  g_part[2][B][PB][MP];         // double-buffered column partials
__device__ float  g_errpart[2][GRID];
__device__ float  g_costpart[GRID];
__device__ int          g_cnt;
__device__ volatile int g_gen;

// -------- software grid barrier (128 blocks, 1/SM, guaranteed resident) -----
__device__ __forceinline__ void gridbar() {
    __syncthreads();
    if (threadIdx.x == 0) {
        __threadfence();
        int g = g_gen;
        if (atomicAdd(&g_cnt, 1) == GRID - 1) {
            g_cnt = 0;
            __threadfence();
            g_gen = g + 1;
        } else {
            while (g_gen == g) __nanosleep(64);
        }
        __threadfence();
    }
    __syncthreads();
}

__device__ __forceinline__ void h8_to_f8(const uint4 v, float* f) {
    float2 a = __half22float2(*(const __half2*)&v.x);
    float2 b = __half22float2(*(const __half2*)&v.y);
    float2 c = __half22float2(*(const __half2*)&v.z);
    float2 d = __half22float2(*(const __half2*)&v.w);
    f[0]=a.x; f[1]=a.y; f[2]=b.x; f[3]=b.y; f[4]=c.x; f[5]=c.y; f[6]=d.x; f[7]=d.y;
}

__global__ void __launch_bounds__(TPB, 1)
k_sinkhorn(const float* __restrict__ C, float* __restrict__ out)
{
    __shared__ float sb[MP];             // current b (exp(v/eps)) for this batch
    __shared__ float sT[8][MP];          // per-warp column partials
    __shared__ float sU[RPB];
    __shared__ float sA[RPB];
    __shared__ float sred[TPB];

    const int bid = blockIdx.x;
    const int b   = bid >> 3;            // batch 0..15
    const int ib  = bid & 7;             // block-in-batch 0..7
    const int tid = threadIdx.x;
    const int w   = tid >> 5;            // warp 0..7
    const int l   = tid & 31;
    const int rowBase = (b << 10) + (ib << 7);   // 128 rows per block
    const int wrow    = rowBase + w * RPW;       // this warp's 16 rows

    const float MU   = 1.0f / 1024.0f + 1e-8f;
    const float LOGM = logf(MU);

    if (tid < RPB) { sU[tid] = 0.f; sA[tid] = 0.f; }
    ((float4*)sb)[tid] = make_float4(1.f, 1.f, 1.f, 1.f);   // b0 = 1
    __syncthreads();

    uint4*        K4 = (uint4*)g_Kh;     // 8 halfs/uint4, 128 uint4 per row
    const float4* C4 = (const float4*)C; // 256 float4 per row

    float*  outCost = out;
    float4* outPi   = (float4*)(out + B);
    float4* outC    = (float4*)(out + B + (size_t)B * N * MP);

    int par = 0, copied = 0;
    for (int t = 0; t < MAX_ITER; t++) {
        // -------- cache b in registers: lane covers cols (k*32+l)*8 + e -----
        float bb[4][8];
        #pragma unroll
        for (int k = 0; k < 4; k++) {
            float4 p0 = ((const float4*)sb)[(((k << 5) + l) << 1)];
            float4 p1 = ((const float4*)sb)[(((k << 5) + l) << 1) + 1];
            bb[k][0]=p0.x; bb[k][1]=p0.y; bb[k][2]=p0.z; bb[k][3]=p0.w;
            bb[k][4]=p1.x; bb[k][5]=p1.y; bb[k][6]=p1.z; bb[k][7]=p1.w;
        }
        float Tacc[4][8];
        #pragma unroll
        for (int k = 0; k < 4; k++)
            #pragma unroll
            for (int e = 0; e < 8; e++) Tacc[k][e] = 0.f;
        float du = 0.f;

        if (t == 0) {
            // ---- first pass: build fp16 K, C loads software-pipelined ----
            float4 c0a[4], c1a[4];
            {
                size_t qb = (size_t)wrow << 7;
                #pragma unroll
                for (int k = 0; k < 4; k++) {
                    size_t q = qb + (k << 5) + l;
                    c0a[k] = C4[q << 1];
                    c1a[k] = C4[(q << 1) + 1];
                }
            }
            for (int r = 0; r < RPW; r++) {
                float4 c0n[4], c1n[4];
                if (r + 1 < RPW) {                 // prefetch next row's C
                    size_t qn = (size_t)(wrow + r + 1) << 7;
                    #pragma unroll
                    for (int k = 0; k < 4; k++) {
                        size_t q = qn + (k << 5) + l;
                        c0n[k] = C4[q << 1];
                        c1n[k] = C4[(q << 1) + 1];
                    }
                }
                size_t qb = (size_t)(wrow + r) << 7;
                float kf[4][8];
                #pragma unroll
                for (int k = 0; k < 4; k++) {
                    kf[k][0]=__expf(-c0a[k].x*INV_EPS); kf[k][1]=__expf(-c0a[k].y*INV_EPS);
                    kf[k][2]=__expf(-c0a[k].z*INV_EPS); kf[k][3]=__expf(-c0a[k].w*INV_EPS);
                    kf[k][4]=__expf(-c1a[k].x*INV_EPS); kf[k][5]=__expf(-c1a[k].y*INV_EPS);
                    kf[k][6]=__expf(-c1a[k].z*INV_EPS); kf[k][7]=__expf(-c1a[k].w*INV_EPS);
                    uint4 kv;
                    __half2 h;
                    h=__floats2half2_rn(kf[k][0],kf[k][1]); kv.x=*(unsigned*)&h;
                    h=__floats2half2_rn(kf[k][2],kf[k][3]); kv.y=*(unsigned*)&h;
                    h=__floats2half2_rn(kf[k][4],kf[k][5]); kv.z=*(unsigned*)&h;
                    h=__floats2half2_rn(kf[k][6],kf[k][7]); kv.w=*(unsigned*)&h;
                    K4[qb + (k << 5) + l] = kv;
                    // use fp16-rounded values so iterations are consistent
                    h8_to_f8(kv, kf[k]);
                }
                float s = 0.f;
                #pragma unroll
                for (int k = 0; k < 4; k++)
                    #pragma unroll
                    for (int e = 0; e < 8; e++) s = fmaf(kf[k][e], bb[k][e], s);
                #pragma unroll
                for (int o = 16; o; o >>= 1) s += __shfl_xor_sync(~0u, s, o);
                float a = MU / s;
                if (l == 0) {
                    float unew = EPS_F * (LOGM - logf(s));
                    int ri = w * RPW + r;
                    du += fabsf(unew - sU[ri]);
                    sU[ri] = unew; sA[ri] = a;
                }
                #pragma unroll
                for (int k = 0; k < 4; k++)
                    #pragma unroll
                    for (int e = 0; e < 8; e++)
                        Tacc[k][e] = fmaf(a, kf[k][e], Tacc[k][e]);
                if (r + 1 < RPW) {
                    #pragma unroll
                    for (int k = 0; k < 4; k++) { c0a[k] = c0n[k]; c1a[k] = c1n[k]; }
                }
            }
        } else {
            // ---- steady state: fp16 K, double-buffered loads (R8 proven) ----
            uint4 kq[4];
            {
                size_t qb = (size_t)wrow << 7;
                #pragma unroll
                for (int k = 0; k < 4; k++) kq[k] = K4[qb + (k << 5) + l];
            }
            for (int r = 0; r < RPW; r++) {
                uint4 kn[4];
                if (r + 1 < RPW) {
                    size_t qn = (size_t)(wrow + r + 1) << 7;
                    #pragma unroll
                    for (int k = 0; k < 4; k++) kn[k] = K4[qn + (k << 5) + l];
                }
                float kf[4][8];
                #pragma unroll
                for (int k = 0; k < 4; k++) h8_to_f8(kq[k], kf[k]);
                float s = 0.f;
                #pragma unroll
                for (int k = 0; k < 4; k++)
                    #pragma unroll
                    for (int e = 0; e < 8; e++) s = fmaf(kf[k][e], bb[k][e], s);
                #pragma unroll
                for (int o = 16; o; o >>= 1) s += __shfl_xor_sync(~0u, s, o);
                float a = MU / s;
                if (l == 0) {
                    float unew = EPS_F * (LOGM - logf(s));
                    int ri = w * RPW + r;
                    du += fabsf(unew - sU[ri]);
                    sU[ri] = unew; sA[ri] = a;
                }
                #pragma unroll
                for (int k = 0; k < 4; k++)
                    #pragma unroll
                    for (int e = 0; e < 8; e++)
                        Tacc[k][e] = fmaf(a, kf[k][e], Tacc[k][e]);
                if (r + 1 < RPW) {
                    #pragma unroll
                    for (int k = 0; k < 4; k++) kq[k] = kn[k];
                }
            }
        }

        // -------- block-combine 8 warps' column partials (deterministic) ----
        {
            float4* me = (float4*)sT[w];
            #pragma unroll
            for (int k = 0; k < 4; k++) {
                me[(((k << 5) + l) << 1)]     = make_float4(Tacc[k][0], Tacc[k][1], Tacc[k][2], Tacc[k][3]);
                me[(((k << 5) + l) << 1) + 1] = make_float4(Tacc[k][4], Tacc[k][5], Tacc[k][6], Tacc[k][7]);
            }
            if (l == 0) sred[w] = du;
        }
        __syncthreads();
        {
            float4 Tj = ((const float4*)sT[0])[tid];
            #pragma unroll
            for (int ww = 1; ww < 8; ww++) {
                float4 x = ((const float4*)sT[ww])[tid];
                Tj.x += x.x; Tj.y += x.y; Tj.z += x.z; Tj.w += x.w;
            }
            ((float4*)g_part[par][b][ib])[tid] = Tj;
        }
        if (tid == 0) {
            float e = 0.f;
            #pragma unroll
            for (int ww = 0; ww < 8; ww++) e += sred[ww];
            g_errpart[par][bid] = e;
        }

        // -------- barrier-shadow outC copy: one 16-row chunk per iteration --
        if (t >= 1 && copied < 8) {
            size_t base = ((size_t)(rowBase + (copied << 4) + (tid >> 4))) * 256
                        + (tid & 15);
            #pragma unroll
            for (int j = 0; j < 16; j++) {
                float4 v = C4[base + j * 16];
                __stcs(outC + base + j * 16, v);
            }
            copied++;
        }

        gridbar();

        // -------- v update: combine 8 block-partials (redundant per block) --
        float4 T = make_float4(0.f, 0.f, 0.f, 0.f);
        #pragma unroll
        for (int kk = 0; kk < PB; kk++) {
            float4 x = __ldcg(((const float4*)g_part[par][b][kk]) + tid);
            T.x += x.x; T.y += x.y; T.z += x.z; T.w += x.w;
        }
        float4 bbn;
        bbn.x = MU / T.x; bbn.y = MU / T.y; bbn.z = MU / T.z; bbn.w = MU / T.w;

        // deterministic err reduction
        sred[tid] = (tid < GRID) ? __ldcg(&g_errpart[par][tid]) : 0.f;
        __syncthreads();
        for (int o = 128; o; o >>= 1) {
            if (tid < o) sred[tid] += sred[tid + o];
            __syncthreads();
        }
        float err = sred[0];

        ((float4*)sb)[tid] = bbn;
        __syncthreads();

        if (err < 0.1f * (float)B) break;    // err/B < THRESH
        par ^= 1;
    }

    // ============= Epilogue: pipelined C loads; pi, cost, remaining outC ====
    const float4* sb4 = (const float4*)sb;
    const bool doC = (w >= copied);          // warps whose chunk wasn't copied

    float cost = 0.f;
    float4 cc[8];
    {
        size_t f4 = (size_t)wrow << 8;
        #pragma unroll
        for (int k = 0; k < 8; k++) cc[k] = C4[f4 + (k << 5) + l];
    }
    for (int r = 0; r < RPW; r++) {
        int row = wrow + r;
        size_t f4 = (size_t)row << 8;
        float4 cn[8];
        if (r + 1 < RPW) {                   // prefetch next row's C
            size_t fn = (size_t)(row + 1) << 8;
            #pragma unroll
            for (int k = 0; k < 8; k++) cn[k] = C4[fn + (k << 5) + l];
        }
        float a = sA[w * RPW + r];
        #pragma unroll
        for (int k = 0; k < 8; k++) {
            int q = (k << 5) + l;
            float4 c  = cc[k];
            float4 bv = sb4[q];
            float4 p;
            p.x = a * bv.x * __expf(-c.x * INV_EPS);
            p.y = a * bv.y * __expf(-c.y * INV_EPS);
            p.z = a * bv.z * __expf(-c.z * INV_EPS);
            p.w = a * bv.w * __expf(-c.w * INV_EPS);
            outPi[f4 + q] = p;
            if (doC) outC[f4 + q] = c;
            cost += p.x * c.x + p.y * c.y + p.z * c.z + p.w * c.w;
        }
        if (r + 1 < RPW) {
            #pragma unroll
            for (int k = 0; k < 8; k++) cc[k] = cn[k];
        }
    }
    sred[tid] = cost;
    __syncthreads();
    for (int o = 128; o; o >>= 1) {
        if (tid < o) sred[tid] += sred[tid + o];
        __syncthreads();
    }
    if (tid == 0) g_costpart[bid] = sred[0];

    gridbar();

    if (bid == 0 && tid < B) {               // deterministic final cost sum
        float cs = 0.f;
        #pragma unroll
        for (int kk = 0; kk < PB; kk++)
            cs += __ldcg(&g_costpart[(tid << 3) + kk]);
        outCost[tid] = cs;
    }
}

// ---------------- launch -----------------------------------------------------
extern "C" void kernel_launch(void* const* d_in, const int* in_sizes, int n_in,
                              void* d_out, int out_size) {
    const float* C = nullptr;
    for (int i = 0; i < n_in; i++)
        if (in_sizes[i] == B * N * MP) C = (const float*)d_in[i];
    k_sinkhorn<<<GRID, TPB>>>(C, (float*)d_out);
    (void)out_size;
}